// round 14
// baseline (speedup 1.0000x reference)
#include <cuda_runtime.h>
#include <cstdint>

// Problem constants
#define N_BATCH 16
#define C_IN    256
#define H_IMG   128
#define W_IMG   128
#define HW      (H_IMG * W_IMG)
#define GROUPS  8
#define CPG     32          // channels per group
#define KK      9           // 3x3 taps
#define OC      72          // GROUPS*KK
#define BN_EPS  1e-5f

// Exp(logit) scratch: 16*72*128*128 floats = 75.5 MB (K1 stores exp directly)
__device__ float g_elog[(size_t)N_BATCH * OC * HW];
// Per-group sum of exp(logit): 16*8*128*128 floats = 8.4 MB
__device__ float g_expsum[(size_t)N_BATCH * GROUPS * HW];

// ---------------- f32x2 helpers (Blackwell packed fp32 FMA) ----------------
__device__ __forceinline__ void fma2(unsigned long long& d,
                                     unsigned long long a,
                                     unsigned long long b) {
    asm("fma.rn.f32x2 %0, %1, %2, %0;" : "+l"(d) : "l"(a), "l"(b));
}
__device__ __forceinline__ unsigned long long pack2(float lo, float hi) {
    unsigned long long r;
    asm("mov.b64 %0, {%1, %2};" : "=l"(r) : "f"(lo), "f"(hi));
    return r;
}
__device__ __forceinline__ void unpack2(unsigned long long v, float& lo, float& hi) {
    asm("mov.b64 {%0, %1}, %2;" : "=f"(lo), "=f"(hi) : "l"(v));
}

__device__ __forceinline__ int refl(int v) {
    return v < 0 ? -v : (v > (H_IMG - 1) ? 2 * (H_IMG - 1) - v : v);
}

__device__ __forceinline__ uint32_t smem_u32(const void* p) {
    uint32_t a;
    asm("{ .reg .u64 t; cvta.to.shared.u64 t, %1; cvt.u32.u64 %0, t; }"
        : "=r"(a) : "l"(p));
    return a;
}
__device__ __forceinline__ void cp_async4(uint32_t dst, const float* src) {
    asm volatile("cp.async.ca.shared.global [%0], [%1], 4;"
                 :: "r"(dst), "l"(src) : "memory");
}
__device__ __forceinline__ void cp_commit() {
    asm volatile("cp.async.commit_group;" ::: "memory");
}
__device__ __forceinline__ void cp_wait2() {
    asm volatile("cp.async.wait_group 2;" ::: "memory");
}
__device__ __forceinline__ void cp_wait1() {
    asm volatile("cp.async.wait_group 1;" ::: "memory");
}
__device__ __forceinline__ void cp_wait0() {
    asm volatile("cp.async.wait_group 0;" ::: "memory");
}

// ============================================================================
// K1: grouped conv 3x3 (reflect) + BN -> exp(logits) + per-group expsum.
// 16x64 tile, 128 threads, 8 px/thread. cp.async double buffer (distance 1 —
// compute-bound, FMA phase covers latency). smem 40.3KB -> 4 blocks/SM.
// ============================================================================
#define K1_TW 64
#define K1_TH 16
#define K1_HALO_R 18
#define K1_HALO_C 66
#define K1_NQ (K1_HALO_R * K1_HALO_C)        // 1188
#define K1_XST 68
#define K1_CHST (K1_HALO_R * K1_XST)         // 1224
#define K1_CHUNK 2
#define K1_NCHUNK (CPG / K1_CHUNK)           // 16
#define K1_BUF_WORDS (K1_CHUNK * K1_CHST)    // 2448
#define K1_WS_BYTES (KK * CPG * KK * 8)                  // 20736
#define K1_SMEM (K1_WS_BYTES + 2 * K1_BUF_WORDS * 4)     // 40320

__global__ void __launch_bounds__(128, 4)
k1_conv_bn(const float* __restrict__ x,
           const float* __restrict__ w,
           const float* __restrict__ gamma,
           const float* __restrict__ beta,
           const float* __restrict__ mean,
           const float* __restrict__ var) {
    extern __shared__ char smem[];
    float2* ws2  = (float2*)smem;                               // [9][32][9]
    float*  bufs = (float*)(smem + K1_WS_BYTES);                // [2][2][1224]

    const int n  = blockIdx.z >> 3;
    const int g  = blockIdx.z & 7;
    const int bx = blockIdx.x * K1_TW;
    const int by = blockIdx.y * K1_TH;
    const int tid = threadIdx.x;
    const int row = tid >> 3;
    const int xq  = (tid & 7) << 3;

    // Register reflect-address tables (10 halo entries per thread)
    int sQ[10], dQ[10];
#pragma unroll
    for (int e = 0; e < 10; e++) {
        int q = tid + e * 128;
        bool ok = (q < K1_NQ);
        int qc = ok ? q : 0;
        int rr = qc / K1_HALO_C;
        int cc = qc - rr * K1_HALO_C;
        sQ[e] = refl(by + rr - 1) * W_IMG + refl(bx + cc - 1);
        dQ[e] = rr * K1_XST + cc;
    }
    const bool hasLast = (tid + 9 * 128) < K1_NQ;
    const uint32_t sbase = smem_u32(bufs);

    // BN-scaled duplicated weights: ws2[o*288 + ci*9 + t]
    for (int i = tid; i < KK * CPG * KK; i += 128) {
        int o  = i / (CPG * KK);
        int oc = g * KK + o;
        float sc = gamma[oc] * rsqrtf(var[oc] + BN_EPS);
        float wv = w[(size_t)oc * (CPG * KK) + (i % (CPG * KK))] * sc;
        ws2[i] = make_float2(wv, wv);
    }

    unsigned long long acc[9][4];
#pragma unroll
    for (int o = 0; o < 9; o++) {
        int oc = g * KK + o;
        float sc = gamma[oc] * rsqrtf(var[oc] + BN_EPS);
        float sh = beta[oc] - mean[oc] * sc;
        unsigned long long p = pack2(sh, sh);
#pragma unroll
        for (int j = 0; j < 4; j++) acc[o][j] = p;
    }

    const float* xg = x + (size_t)(n * C_IN + g * CPG) * HW;

    // Prefetch chunk 0 into buffer 0
#pragma unroll
    for (int ci = 0; ci < K1_CHUNK; ci++) {
        const float* c = xg + (size_t)ci * HW;
        uint32_t boff = (uint32_t)(ci * K1_CHST * 4);
#pragma unroll
        for (int e = 0; e < 9; e++)
            cp_async4(sbase + boff + dQ[e] * 4, c + sQ[e]);
        if (hasLast) cp_async4(sbase + boff + dQ[9] * 4, c + sQ[9]);
    }
    cp_commit();

#pragma unroll 1
    for (int chunk = 0; chunk < K1_NCHUNK; chunk++) {
        if (chunk < K1_NCHUNK - 1) {
            const uint32_t bufoff = (uint32_t)((((chunk + 1) & 1)) * K1_BUF_WORDS * 4);
#pragma unroll
            for (int ci = 0; ci < K1_CHUNK; ci++) {
                const float* c = xg + (size_t)((chunk + 1) * K1_CHUNK + ci) * HW;
                uint32_t boff = bufoff + (uint32_t)(ci * K1_CHST * 4);
#pragma unroll
                for (int e = 0; e < 9; e++)
                    cp_async4(sbase + boff + dQ[e] * 4, c + sQ[e]);
                if (hasLast) cp_async4(sbase + boff + dQ[9] * 4, c + sQ[9]);
            }
            cp_commit();
            cp_wait1();
        } else {
            cp_wait0();
        }
        __syncthreads();   // chunk data fully visible (also covers ws2 on iter 0)

        const float* xsb = bufs + (chunk & 1) * K1_BUF_WORDS;
#pragma unroll
        for (int ci = 0; ci < K1_CHUNK; ci++) {
            const int cig = chunk * K1_CHUNK + ci;
            const float* xrow = xsb + ci * K1_CHST + row * K1_XST + xq;
            const unsigned long long* wb =
                (const unsigned long long*)(ws2) + cig * KK;

#pragma unroll
            for (int r3 = 0; r3 < 3; r3++) {
                float v[10];
                const float4 a0 = *(const float4*)(xrow + r3 * K1_XST);
                const float4 a1 = *(const float4*)(xrow + r3 * K1_XST + 4);
                const float2 a2 = *(const float2*)(xrow + r3 * K1_XST + 8);
                v[0]=a0.x; v[1]=a0.y; v[2]=a0.z; v[3]=a0.w;
                v[4]=a1.x; v[5]=a1.y; v[6]=a1.z; v[7]=a1.w;
                v[8]=a2.x; v[9]=a2.y;

                unsigned long long p[3][4];
#pragma unroll
                for (int c3 = 0; c3 < 3; c3++)
#pragma unroll
                    for (int j = 0; j < 4; j++)
                        p[c3][j] = pack2(v[c3 + 2 * j], v[c3 + 2 * j + 1]);

#pragma unroll
                for (int o = 0; o < 9; o++) {
                    const unsigned long long* wr = wb + o * (CPG * KK) + r3 * 3;
                    unsigned long long w0 = wr[0], w1 = wr[1], w2 = wr[2];
#pragma unroll
                    for (int j = 0; j < 4; j++) fma2(acc[o][j], p[0][j], w0);
#pragma unroll
                    for (int j = 0; j < 4; j++) fma2(acc[o][j], p[1][j], w1);
#pragma unroll
                    for (int j = 0; j < 4; j++) fma2(acc[o][j], p[2][j], w2);
                }
            }
        }
        __syncthreads();   // buffer consumed before it is prefetch-overwritten
    }

    // Epilogue: store EXP(logit) + per-group expsum (exps computed anyway)
    float esum[8] = {0, 0, 0, 0, 0, 0, 0, 0};
    float* lp = g_elog + ((size_t)(n * OC + g * KK) * H_IMG + (by + row)) * W_IMG + bx + xq;
#pragma unroll
    for (int o = 0; o < 9; o++) {
        float4 r0, r1;
        unpack2(acc[o][0], r0.x, r0.y);
        unpack2(acc[o][1], r0.z, r0.w);
        unpack2(acc[o][2], r1.x, r1.y);
        unpack2(acc[o][3], r1.z, r1.w);
        float4 e0 = make_float4(__expf(r0.x), __expf(r0.y), __expf(r0.z), __expf(r0.w));
        float4 e1 = make_float4(__expf(r1.x), __expf(r1.y), __expf(r1.z), __expf(r1.w));
        *(float4*)(lp + (size_t)o * HW)     = e0;
        *(float4*)(lp + (size_t)o * HW + 4) = e1;
        esum[0] += e0.x; esum[1] += e0.y; esum[2] += e0.z; esum[3] += e0.w;
        esum[4] += e1.x; esum[5] += e1.y; esum[6] += e1.z; esum[7] += e1.w;
    }
    float* ep = g_expsum + ((size_t)(n * GROUPS + g) * H_IMG + (by + row)) * W_IMG + bx + xq;
    *(float4*)ep       = make_float4(esum[0], esum[1], esum[2], esum[3]);
    *(float4*)(ep + 4) = make_float4(esum[4], esum[5], esum[6], esum[7]);
}

// ============================================================================
// K3: softmax weights (stored exps / expsum) + weighted 3x3 gather.
// 8x64 tile, 256 threads, 2 px/thread; each block handles 4 of the 8 groups
// (1024 blocks -> better chip balance). cp.async 3-buffer ring, distance 2.
// smem 32.6KB, <=64 regs -> 4 blocks/SM.
// ============================================================================
#define K3_TW 64
#define K3_TH 8
#define K3_HALO_R 10
#define K3_HALO_C 66
#define K3_NQ (K3_HALO_R * K3_HALO_C)    // 660
#define K3_XST 68
#define K3_CHST (K3_HALO_R * K3_XST)     // 680 words per channel
#define K3_BATCH 4
#define K3_NT 32                         // 32 batches: 4 groups x 8 batches
#define K3_BUF_WORDS (K3_BATCH * K3_CHST)   // 2720
#define K3_SMEM (3 * K3_BUF_WORDS * 4)      // 32640

__global__ void __launch_bounds__(256, 4)
k3_softmax_gather(const float* __restrict__ x, float* __restrict__ out) {
    extern __shared__ char smem[];
    float* bufs = (float*)smem;          // [3][4][680]

    const int n    = blockIdx.z >> 1;
    const int g0   = (blockIdx.z & 1) * 4;   // group base for this block
    const int bx = blockIdx.x * K3_TW;
    const int by = blockIdx.y * K3_TH;
    const int tid = threadIdx.x;
    const int ty = tid >> 5;             // 0..7  (warp = one pixel row)
    const int tx = tid & 31;             // cols 2tx, 2tx+1

    // Register reflect-address tables (<=3 entries/thread)
    int sQ[3], dQ[3];
#pragma unroll
    for (int e = 0; e < 3; e++) {
        int q = tid + e * 256;
        int qc = (q < K3_NQ) ? q : 0;
        int rr = qc / K3_HALO_C;
        int cc = qc - rr * K3_HALO_C;
        sQ[e] = refl(by + rr - 1) * W_IMG + refl(bx + cc - 1);
        dQ[e] = rr * K3_XST + cc;
    }
    const bool has3 = (tid + 512) < K3_NQ;

    const float* xb = x + (size_t)n * C_IN * HW;
    const uint32_t sb = smem_u32(bufs);
    const uint32_t du0 = sb + dQ[0] * 4;
    const uint32_t du1 = sb + dQ[1] * 4;
    const uint32_t du2 = sb + dQ[2] * 4;

    // Fill pipeline: batches 0 and 1 (channels of group g0)
#pragma unroll
    for (int pt = 0; pt < 2; pt++) {
        const uint32_t bufoff = (uint32_t)(pt * K3_BUF_WORDS * 4);
        const int chp = g0 * CPG + pt * K3_BATCH;
#pragma unroll
        for (int ci = 0; ci < K3_BATCH; ci++) {
            const float* c = xb + (size_t)(chp + ci) * HW;
            uint32_t boff = bufoff + (uint32_t)(ci * K3_CHST * 4);
            cp_async4(du0 + boff, c + sQ[0]);
            cp_async4(du1 + boff, c + sQ[1]);
            if (has3) cp_async4(du2 + boff, c + sQ[2]);
        }
        cp_commit();
    }

    // Softmax denominator from K1's per-group expsums (all 8 groups)
    const float* eb = g_expsum + ((size_t)(n * GROUPS) * H_IMG + (by + ty)) * W_IMG
                    + bx + 2 * tx;
    float s0 = 0.f, s1 = 0.f;
#pragma unroll
    for (int g = 0; g < 8; g++) {
        float2 ev = *(const float2*)(eb + (size_t)g * HW);
        s0 += ev.x;
        s1 += ev.y;
    }
    const float inv0 = 1.0f / s0;
    const float inv1 = 1.0f / s1;

    const float* lbase = g_elog + ((size_t)n * OC * H_IMG + (by + ty)) * W_IMG
                        + bx + 2 * tx;
    float* ob = out + (size_t)n * C_IN * HW + (size_t)(by + ty) * W_IMG + bx + 2 * tx;
    const int gbase = ty * K3_XST + 2 * tx;

    float sg0[9], sg1[9];
    int bcur = 0;

#pragma unroll 1
    for (int t = 0; t < K3_NT; t++) {
        const int g = g0 + (t >> 3);

        // sig for this group: stored exp * inv (no expf in K3)
        if ((t & 7) == 0) {
#pragma unroll
            for (int k = 0; k < 9; k++) {
                float2 lv = *(const float2*)(lbase + (size_t)(g * 9 + k) * HW);
                sg0[k] = lv.x * inv0;
                sg1[k] = lv.y * inv1;
            }
        }

        // Prefetch batch t+2 into the buffer freed at iter t-1
        if (t + 2 < K3_NT) {
            const int tt = t + 2;
            const int ch2 = (g0 + (tt >> 3)) * CPG + (tt & 7) * K3_BATCH;
            int bp = bcur + 2; if (bp >= 3) bp -= 3;
            const uint32_t bufoff = (uint32_t)(bp * K3_BUF_WORDS * 4);
#pragma unroll
            for (int ci = 0; ci < K3_BATCH; ci++) {
                const float* c = xb + (size_t)(ch2 + ci) * HW;
                uint32_t boff = bufoff + (uint32_t)(ci * K3_CHST * 4);
                cp_async4(du0 + boff, c + sQ[0]);
                cp_async4(du1 + boff, c + sQ[1]);
                if (has3) cp_async4(du2 + boff, c + sQ[2]);
            }
            cp_commit();
            cp_wait2();
        } else if (t + 2 == K3_NT) {
            cp_wait1();
        } else {
            cp_wait0();
        }
        __syncthreads();   // batch t visible

        // Compute batch t
        const float* xbuf = bufs + bcur * K3_BUF_WORDS;
        const int ch = g * CPG + (t & 7) * K3_BATCH;
        float* op = ob + (size_t)ch * HW;
#pragma unroll
        for (int ci = 0; ci < K3_BATCH; ci++) {
            const float* xp = xbuf + ci * K3_CHST + gbase;
            const float2 a0 = *(const float2*)(xp);
            const float2 a1 = *(const float2*)(xp + 2);
            const float2 b0 = *(const float2*)(xp + K3_XST);
            const float2 b1 = *(const float2*)(xp + K3_XST + 2);
            const float2 c0 = *(const float2*)(xp + 2 * K3_XST);
            const float2 c1 = *(const float2*)(xp + 2 * K3_XST + 2);

            float acc0 = sg0[0] * a0.x + sg0[1] * a0.y + sg0[2] * a1.x
                       + sg0[3] * b0.x + sg0[4] * b0.y + sg0[5] * b1.x
                       + sg0[6] * c0.x + sg0[7] * c0.y + sg0[8] * c1.x;
            float acc1 = sg1[0] * a0.y + sg1[1] * a1.x + sg1[2] * a1.y
                       + sg1[3] * b0.y + sg1[4] * b1.x + sg1[5] * b1.y
                       + sg1[6] * c0.y + sg1[7] * c1.x + sg1[8] * c1.y;

            *(float2*)(op + (size_t)ci * HW) = make_float2(acc0, acc1);
        }
        __syncthreads();   // buffer consumed; safe for a later prefetch
        bcur = (bcur + 1 == 3) ? 0 : bcur + 1;
    }
}

// ============================================================================
extern "C" void kernel_launch(void* const* d_in, const int* in_sizes, int n_in,
                              void* d_out, int out_size) {
    const float* x     = (const float*)d_in[0];
    const float* w     = (const float*)d_in[1];
    const float* gamma = (const float*)d_in[2];
    const float* beta  = (const float*)d_in[3];
    const float* mean  = (const float*)d_in[4];
    const float* var   = (const float*)d_in[5];
    float* out = (float*)d_out;

    cudaFuncSetAttribute(k1_conv_bn,
                         cudaFuncAttributeMaxDynamicSharedMemorySize, K1_SMEM);
    cudaFuncSetAttribute(k3_softmax_gather,
                         cudaFuncAttributeMaxDynamicSharedMemorySize, K3_SMEM);

    dim3 g1(W_IMG / K1_TW, H_IMG / K1_TH, N_BATCH * GROUPS);   // (2, 8, 128)
    k1_conv_bn<<<g1, 128, K1_SMEM>>>(x, w, gamma, beta, mean, var);

    dim3 g3(W_IMG / K3_TW, H_IMG / K3_TH, N_BATCH * 2);        // (2, 16, 32)
    k3_softmax_gather<<<g3, 256, K3_SMEM>>>(x, out);
}

// round 15
// speedup vs baseline: 1.0306x; 1.0306x over previous
#include <cuda_runtime.h>
#include <cstdint>

// Problem constants
#define N_BATCH 16
#define C_IN    256
#define H_IMG   128
#define W_IMG   128
#define HW      (H_IMG * W_IMG)
#define GROUPS  8
#define CPG     32          // channels per group
#define KK      9           // 3x3 taps
#define OC      72          // GROUPS*KK
#define BN_EPS  1e-5f

// Exp(logit) scratch: 16*72*128*128 floats = 75.5 MB (K1 stores exp directly)
__device__ float g_elog[(size_t)N_BATCH * OC * HW];
// Per-group sum of exp(logit): 16*8*128*128 floats = 8.4 MB
__device__ float g_expsum[(size_t)N_BATCH * GROUPS * HW];

// ---------------- f32x2 helpers (Blackwell packed fp32 FMA) ----------------
__device__ __forceinline__ void fma2(unsigned long long& d,
                                     unsigned long long a,
                                     unsigned long long b) {
    asm("fma.rn.f32x2 %0, %1, %2, %0;" : "+l"(d) : "l"(a), "l"(b));
}
__device__ __forceinline__ unsigned long long pack2(float lo, float hi) {
    unsigned long long r;
    asm("mov.b64 %0, {%1, %2};" : "=l"(r) : "f"(lo), "f"(hi));
    return r;
}
__device__ __forceinline__ void unpack2(unsigned long long v, float& lo, float& hi) {
    asm("mov.b64 {%0, %1}, %2;" : "=f"(lo), "=f"(hi) : "l"(v));
}

__device__ __forceinline__ int refl(int v) {
    return v < 0 ? -v : (v > (H_IMG - 1) ? 2 * (H_IMG - 1) - v : v);
}

__device__ __forceinline__ uint32_t smem_u32(const void* p) {
    uint32_t a;
    asm("{ .reg .u64 t; cvta.to.shared.u64 t, %1; cvt.u32.u64 %0, t; }"
        : "=r"(a) : "l"(p));
    return a;
}
__device__ __forceinline__ void cp_async4(uint32_t dst, const float* src) {
    asm volatile("cp.async.ca.shared.global [%0], [%1], 4;"
                 :: "r"(dst), "l"(src) : "memory");
}
__device__ __forceinline__ void cp_async16(uint32_t dst, const float* src) {
    asm volatile("cp.async.ca.shared.global [%0], [%1], 16;"
                 :: "r"(dst), "l"(src) : "memory");
}
__device__ __forceinline__ void cp_commit() {
    asm volatile("cp.async.commit_group;" ::: "memory");
}
__device__ __forceinline__ void cp_wait1() {
    asm volatile("cp.async.wait_group 1;" ::: "memory");
}
__device__ __forceinline__ void cp_wait0() {
    asm volatile("cp.async.wait_group 0;" ::: "memory");
}

// ============================================================================
// K1: grouped conv 3x3 (reflect) + BN -> exp(logits) + per-group expsum.
// 16x64 tile, 128 threads, 8 px/thread. cp.async double buffer, distance 1,
// single __syncthreads per chunk (prefetch issued after the sync).
// smem 40.3KB -> 4 blocks/SM.
// ============================================================================
#define K1_TW 64
#define K1_TH 16
#define K1_HALO_R 18
#define K1_HALO_C 66
#define K1_NQ (K1_HALO_R * K1_HALO_C)        // 1188
#define K1_XST 68
#define K1_CHST (K1_HALO_R * K1_XST)         // 1224
#define K1_CHUNK 2
#define K1_NCHUNK (CPG / K1_CHUNK)           // 16
#define K1_BUF_WORDS (K1_CHUNK * K1_CHST)    // 2448
#define K1_WS_BYTES (KK * CPG * KK * 8)                  // 20736
#define K1_SMEM (K1_WS_BYTES + 2 * K1_BUF_WORDS * 4)     // 40320

__global__ void __launch_bounds__(128, 4)
k1_conv_bn(const float* __restrict__ x,
           const float* __restrict__ w,
           const float* __restrict__ gamma,
           const float* __restrict__ beta,
           const float* __restrict__ mean,
           const float* __restrict__ var) {
    extern __shared__ char smem[];
    float2* ws2  = (float2*)smem;                               // [9][32][9]
    float*  bufs = (float*)(smem + K1_WS_BYTES);                // [2][2][1224]

    const int n  = blockIdx.z >> 3;
    const int g  = blockIdx.z & 7;
    const int bx = blockIdx.x * K1_TW;
    const int by = blockIdx.y * K1_TH;
    const int tid = threadIdx.x;
    const int row = tid >> 3;
    const int xq  = (tid & 7) << 3;

    // Register reflect-address tables (10 halo entries per thread)
    int sQ[10], dQ[10];
#pragma unroll
    for (int e = 0; e < 10; e++) {
        int q = tid + e * 128;
        bool ok = (q < K1_NQ);
        int qc = ok ? q : 0;
        int rr = qc / K1_HALO_C;
        int cc = qc - rr * K1_HALO_C;
        sQ[e] = refl(by + rr - 1) * W_IMG + refl(bx + cc - 1);
        dQ[e] = rr * K1_XST + cc;
    }
    const bool hasLast = (tid + 9 * 128) < K1_NQ;
    const uint32_t sbase = smem_u32(bufs);

    // BN-scaled duplicated weights: ws2[o*288 + ci*9 + t]
    for (int i = tid; i < KK * CPG * KK; i += 128) {
        int o  = i / (CPG * KK);
        int oc = g * KK + o;
        float sc = gamma[oc] * rsqrtf(var[oc] + BN_EPS);
        float wv = w[(size_t)oc * (CPG * KK) + (i % (CPG * KK))] * sc;
        ws2[i] = make_float2(wv, wv);
    }

    unsigned long long acc[9][4];
#pragma unroll
    for (int o = 0; o < 9; o++) {
        int oc = g * KK + o;
        float sc = gamma[oc] * rsqrtf(var[oc] + BN_EPS);
        float sh = beta[oc] - mean[oc] * sc;
        unsigned long long p = pack2(sh, sh);
#pragma unroll
        for (int j = 0; j < 4; j++) acc[o][j] = p;
    }

    const float* xg = x + (size_t)(n * C_IN + g * CPG) * HW;

    // Prefetch chunk 0 into buffer 0
#pragma unroll
    for (int ci = 0; ci < K1_CHUNK; ci++) {
        const float* c = xg + (size_t)ci * HW;
        uint32_t boff = (uint32_t)(ci * K1_CHST * 4);
#pragma unroll
        for (int e = 0; e < 9; e++)
            cp_async4(sbase + boff + dQ[e] * 4, c + sQ[e]);
        if (hasLast) cp_async4(sbase + boff + dQ[9] * 4, c + sQ[9]);
    }
    cp_commit();

#pragma unroll 1
    for (int chunk = 0; chunk < K1_NCHUNK; chunk++) {
        cp_wait0();        // chunk's data (committed one compute-phase ago)
        __syncthreads();   // visible to all; prev buffer fully consumed

        // Prefetch chunk+1 into the other buffer (overlaps compute below)
        if (chunk < K1_NCHUNK - 1) {
            const uint32_t bufoff = (uint32_t)((((chunk + 1) & 1)) * K1_BUF_WORDS * 4);
#pragma unroll
            for (int ci = 0; ci < K1_CHUNK; ci++) {
                const float* c = xg + (size_t)((chunk + 1) * K1_CHUNK + ci) * HW;
                uint32_t boff = bufoff + (uint32_t)(ci * K1_CHST * 4);
#pragma unroll
                for (int e = 0; e < 9; e++)
                    cp_async4(sbase + boff + dQ[e] * 4, c + sQ[e]);
                if (hasLast) cp_async4(sbase + boff + dQ[9] * 4, c + sQ[9]);
            }
            cp_commit();
        }

        const float* xsb = bufs + (chunk & 1) * K1_BUF_WORDS;
#pragma unroll
        for (int ci = 0; ci < K1_CHUNK; ci++) {
            const int cig = chunk * K1_CHUNK + ci;
            const float* xrow = xsb + ci * K1_CHST + row * K1_XST + xq;
            const unsigned long long* wb =
                (const unsigned long long*)(ws2) + cig * KK;

#pragma unroll
            for (int r3 = 0; r3 < 3; r3++) {
                float v[10];
                const float4 a0 = *(const float4*)(xrow + r3 * K1_XST);
                const float4 a1 = *(const float4*)(xrow + r3 * K1_XST + 4);
                const float2 a2 = *(const float2*)(xrow + r3 * K1_XST + 8);
                v[0]=a0.x; v[1]=a0.y; v[2]=a0.z; v[3]=a0.w;
                v[4]=a1.x; v[5]=a1.y; v[6]=a1.z; v[7]=a1.w;
                v[8]=a2.x; v[9]=a2.y;

                unsigned long long p[3][4];
#pragma unroll
                for (int c3 = 0; c3 < 3; c3++)
#pragma unroll
                    for (int j = 0; j < 4; j++)
                        p[c3][j] = pack2(v[c3 + 2 * j], v[c3 + 2 * j + 1]);

#pragma unroll
                for (int o = 0; o < 9; o++) {
                    const unsigned long long* wr = wb + o * (CPG * KK) + r3 * 3;
                    unsigned long long w0 = wr[0], w1 = wr[1], w2 = wr[2];
#pragma unroll
                    for (int j = 0; j < 4; j++) fma2(acc[o][j], p[0][j], w0);
#pragma unroll
                    for (int j = 0; j < 4; j++) fma2(acc[o][j], p[1][j], w1);
#pragma unroll
                    for (int j = 0; j < 4; j++) fma2(acc[o][j], p[2][j], w2);
                }
            }
        }
        __syncthreads();   // chunk consumed before next iter's prefetch reuses buffer
    }

    // Epilogue: store EXP(logit) + per-group expsum
    float esum[8] = {0, 0, 0, 0, 0, 0, 0, 0};
    float* lp = g_elog + ((size_t)(n * OC + g * KK) * H_IMG + (by + row)) * W_IMG + bx + xq;
#pragma unroll
    for (int o = 0; o < 9; o++) {
        float4 r0, r1;
        unpack2(acc[o][0], r0.x, r0.y);
        unpack2(acc[o][1], r0.z, r0.w);
        unpack2(acc[o][2], r1.x, r1.y);
        unpack2(acc[o][3], r1.z, r1.w);
        float4 e0 = make_float4(__expf(r0.x), __expf(r0.y), __expf(r0.z), __expf(r0.w));
        float4 e1 = make_float4(__expf(r1.x), __expf(r1.y), __expf(r1.z), __expf(r1.w));
        *(float4*)(lp + (size_t)o * HW)     = e0;
        *(float4*)(lp + (size_t)o * HW + 4) = e1;
        esum[0] += e0.x; esum[1] += e0.y; esum[2] += e0.z; esum[3] += e0.w;
        esum[4] += e1.x; esum[5] += e1.y; esum[6] += e1.z; esum[7] += e1.w;
    }
    float* ep = g_expsum + ((size_t)(n * GROUPS + g) * H_IMG + (by + row)) * W_IMG + bx + xq;
    *(float4*)ep       = make_float4(esum[0], esum[1], esum[2], esum[3]);
    *(float4*)(ep + 4) = make_float4(esum[4], esum[5], esum[6], esum[7]);
}

// ============================================================================
// K3: softmax weights (stored exps / expsum) + weighted 3x3 gather.
// 8x64 tile, 256 threads, 2 px/thread, 4 groups per block (1024 blocks).
// Staging via 16-BYTE cp.async chunks (halo rows are contiguous in gmem
// except 2 edge columns handled as 4B fixups). Dst layout: halo global col
// gc at word (gc - bx + 4), row stride 72 -> chunk dsts 16B-aligned.
// 3-buffer ring, distance 2, ONE sync per iteration. smem 34.6KB.
// ============================================================================
#define K3_TW 64
#define K3_TH 8
#define K3_HALO_R 10
#define K3_XST 72                        // padded dst row stride (words)
#define K3_CHST (K3_HALO_R * K3_XST)     // 720 words per channel
#define K3_BATCH 4
#define K3_NT 32                         // 4 groups x 8 batches
#define K3_BUF_WORDS (K3_BATCH * K3_CHST)   // 2880
#define K3_SMEM (3 * K3_BUF_WORDS * 4)      // 34560
#define K3_NOPS (K3_HALO_R * 19)            // 190 staging ops per channel

__global__ void __launch_bounds__(256, 4)
k3_softmax_gather(const float* __restrict__ x, float* __restrict__ out) {
    extern __shared__ char smem[];
    float* bufs = (float*)smem;          // [3][4][720]

    const int n    = blockIdx.z >> 1;
    const int g0   = (blockIdx.z & 1) * 4;   // group base for this block
    const int bx = blockIdx.x * K3_TW;       // 0 or 64
    const int by = blockIdx.y * K3_TH;
    const int tid = threadIdx.x;
    const int ty = tid >> 5;             // 0..7  (warp = one pixel row)
    const int tx = tid & 31;             // cols 2tx, 2tx+1

    // --- staging op table (1 op per thread; tid<190 active) ---
    // type: 0=none, 1=cp.async4, 2=cp.async16
    int stype = 0, soff = 0;
    uint32_t dU = 0;     // dst byte offset within a channel
    if (tid < K3_NOPS) {
        int rr = tid / 19;
        int j  = tid - rr * 19;
        int srow = refl(by + rr - 1) * W_IMG;
        if (j < 16) {
            stype = 2;
            int c = (bx == 0 ? 0 : 64) + j * 4;
            soff = srow + c;
            dU = (uint32_t)((rr * K3_XST + j * 4 + 4) * 4);
        } else if (j == 16) {
            stype = 1;
            if (bx == 0) { soff = srow + 64;  dU = (uint32_t)((rr * K3_XST + 68) * 4); }
            else         { soff = srow + 63;  dU = (uint32_t)((rr * K3_XST + 3)  * 4); }
        } else if (j == 17) {
            stype = 1;
            if (bx == 0) { soff = srow + 1;   dU = (uint32_t)((rr * K3_XST + 3)  * 4); }
            else         { soff = srow + 126; dU = (uint32_t)((rr * K3_XST + 68) * 4); }
        }
    }

    const float* xb = x + (size_t)n * C_IN * HW;
    const uint32_t sb = smem_u32(bufs);

    // Fill pipeline: batches 0 and 1 (first channels of group g0)
#pragma unroll
    for (int pt = 0; pt < 2; pt++) {
        const uint32_t bufoff = (uint32_t)(pt * K3_BUF_WORDS * 4);
        const int chp = g0 * CPG + pt * K3_BATCH;
#pragma unroll
        for (int ci = 0; ci < K3_BATCH; ci++) {
            const float* c = xb + (size_t)(chp + ci) * HW;
            uint32_t d = sb + bufoff + (uint32_t)(ci * K3_CHST * 4) + dU;
            if (stype == 2)      cp_async16(d, c + soff);
            else if (stype == 1) cp_async4(d, c + soff);
        }
        cp_commit();
    }

    // Softmax denominator from K1's per-group expsums (overlaps prefetch)
    const float* eb = g_expsum + ((size_t)(n * GROUPS) * H_IMG + (by + ty)) * W_IMG
                    + bx + 2 * tx;
    float s0 = 0.f, s1 = 0.f;
#pragma unroll
    for (int g = 0; g < 8; g++) {
        float2 ev = *(const float2*)(eb + (size_t)g * HW);
        s0 += ev.x;
        s1 += ev.y;
    }
    const float inv0 = 1.0f / s0;
    const float inv1 = 1.0f / s1;

    const float* lbase = g_elog + ((size_t)n * OC * H_IMG + (by + ty)) * W_IMG
                        + bx + 2 * tx;
    float* ob = out + (size_t)n * C_IN * HW + (size_t)(by + ty) * W_IMG + bx + 2 * tx;
    // gather base: dst word for global col (bx+2tx-1) is 2tx+3
    const int gbase = ty * K3_XST + 2 * tx;

    float sg0[9], sg1[9];
    int bcur = 0;

#pragma unroll 1
    for (int t = 0; t < K3_NT; t++) {
        const int g = g0 + (t >> 3);

        if (t + 1 < K3_NT) cp_wait1(); else cp_wait0();
        __syncthreads();   // batch t visible; buffer (bcur+2)%3 fully consumed

        // Prefetch batch t+2 into the buffer freed at iter t-1
        if (t + 2 < K3_NT) {
            const int tt = t + 2;
            const int ch2 = (g0 + (tt >> 3)) * CPG + (tt & 7) * K3_BATCH;
            int bp = bcur + 2; if (bp >= 3) bp -= 3;
            const uint32_t bufoff = (uint32_t)(bp * K3_BUF_WORDS * 4);
#pragma unroll
            for (int ci = 0; ci < K3_BATCH; ci++) {
                const float* c = xb + (size_t)(ch2 + ci) * HW;
                uint32_t d = sb + bufoff + (uint32_t)(ci * K3_CHST * 4) + dU;
                if (stype == 2)      cp_async16(d, c + soff);
                else if (stype == 1) cp_async4(d, c + soff);
            }
            cp_commit();
        }

        // sig for this group: stored exp * inv (no expf in K3)
        if ((t & 7) == 0) {
#pragma unroll
            for (int k = 0; k < 9; k++) {
                float2 lv = *(const float2*)(lbase + (size_t)(g * 9 + k) * HW);
                sg0[k] = lv.x * inv0;
                sg1[k] = lv.y * inv1;
            }
        }

        // Compute batch t
        const float* xbuf = bufs + bcur * K3_BUF_WORDS;
        const int ch = g * CPG + (t & 7) * K3_BATCH;
        float* op = ob + (size_t)ch * HW;
#pragma unroll
        for (int ci = 0; ci < K3_BATCH; ci++) {
            const float* xp = xbuf + ci * K3_CHST + gbase;
            float acc0, acc1;
            {   // row 0: dst words 2tx+3 (scalar), 2tx+4/5 (f0), 2tx+6 (f1.x)
                float  s  = xp[3];
                float2 f0 = *(const float2*)(xp + 4);
                float2 f1 = *(const float2*)(xp + 6);
                acc0 = sg0[0] * s    + sg0[1] * f0.x + sg0[2] * f0.y;
                acc1 = sg1[0] * f0.x + sg1[1] * f0.y + sg1[2] * f1.x;
            }
            {   // row 1
                const float* xr = xp + K3_XST;
                float  s  = xr[3];
                float2 f0 = *(const float2*)(xr + 4);
                float2 f1 = *(const float2*)(xr + 6);
                acc0 += sg0[3] * s    + sg0[4] * f0.x + sg0[5] * f0.y;
                acc1 += sg1[3] * f0.x + sg1[4] * f0.y + sg1[5] * f1.x;
            }
            {   // row 2
                const float* xr = xp + 2 * K3_XST;
                float  s  = xr[3];
                float2 f0 = *(const float2*)(xr + 4);
                float2 f1 = *(const float2*)(xr + 6);
                acc0 += sg0[6] * s    + sg0[7] * f0.x + sg0[8] * f0.y;
                acc1 += sg1[6] * f0.x + sg1[7] * f0.y + sg1[8] * f1.x;
            }
            *(float2*)(op + (size_t)ci * HW) = make_float2(acc0, acc1);
        }
        bcur = (bcur + 1 == 3) ? 0 : bcur + 1;
    }
}

// ============================================================================
extern "C" void kernel_launch(void* const* d_in, const int* in_sizes, int n_in,
                              void* d_out, int out_size) {
    const float* x     = (const float*)d_in[0];
    const float* w     = (const float*)d_in[1];
    const float* gamma = (const float*)d_in[2];
    const float* beta  = (const float*)d_in[3];
    const float* mean  = (const float*)d_in[4];
    const float* var   = (const float*)d_in[5];
    float* out = (float*)d_out;

    cudaFuncSetAttribute(k1_conv_bn,
                         cudaFuncAttributeMaxDynamicSharedMemorySize, K1_SMEM);
    cudaFuncSetAttribute(k3_softmax_gather,
                         cudaFuncAttributeMaxDynamicSharedMemorySize, K3_SMEM);

    dim3 g1(W_IMG / K1_TW, H_IMG / K1_TH, N_BATCH * GROUPS);   // (2, 8, 128)
    k1_conv_bn<<<g1, 128, K1_SMEM>>>(x, w, gamma, beta, mean, var);

    dim3 g3(W_IMG / K3_TW, H_IMG / K3_TH, N_BATCH * 2);        // (2, 16, 32)
    k3_softmax_gather<<<g3, 256, K3_SMEM>>>(x, out);
}

// round 16
// speedup vs baseline: 1.0555x; 1.0241x over previous
#include <cuda_runtime.h>
#include <cstdint>

// Problem constants
#define N_BATCH 16
#define C_IN    256
#define H_IMG   128
#define W_IMG   128
#define HW      (H_IMG * W_IMG)
#define GROUPS  8
#define CPG     32          // channels per group
#define KK      9           // 3x3 taps
#define OC      72          // GROUPS*KK
#define BN_EPS  1e-5f

// Exp(logit) scratch: 16*72*128*128 floats = 75.5 MB (K1 stores exp directly)
__device__ float g_elog[(size_t)N_BATCH * OC * HW];
// Per-group sum of exp(logit): 16*8*128*128 floats = 8.4 MB
__device__ float g_expsum[(size_t)N_BATCH * GROUPS * HW];

// ---------------- f32x2 helpers (Blackwell packed fp32 FMA) ----------------
__device__ __forceinline__ void fma2(unsigned long long& d,
                                     unsigned long long a,
                                     unsigned long long b) {
    asm("fma.rn.f32x2 %0, %1, %2, %0;" : "+l"(d) : "l"(a), "l"(b));
}
__device__ __forceinline__ unsigned long long pack2(float lo, float hi) {
    unsigned long long r;
    asm("mov.b64 %0, {%1, %2};" : "=l"(r) : "f"(lo), "f"(hi));
    return r;
}
__device__ __forceinline__ void unpack2(unsigned long long v, float& lo, float& hi) {
    asm("mov.b64 {%0, %1}, %2;" : "=f"(lo), "=f"(hi) : "l"(v));
}

__device__ __forceinline__ int refl(int v) {
    return v < 0 ? -v : (v > (H_IMG - 1) ? 2 * (H_IMG - 1) - v : v);
}

__device__ __forceinline__ uint32_t smem_u32(const void* p) {
    uint32_t a;
    asm("{ .reg .u64 t; cvta.to.shared.u64 t, %1; cvt.u32.u64 %0, t; }"
        : "=r"(a) : "l"(p));
    return a;
}
__device__ __forceinline__ void cp_async4(uint32_t dst, const float* src) {
    asm volatile("cp.async.ca.shared.global [%0], [%1], 4;"
                 :: "r"(dst), "l"(src) : "memory");
}
__device__ __forceinline__ void cp_commit() {
    asm volatile("cp.async.commit_group;" ::: "memory");
}
__device__ __forceinline__ void cp_wait1() {
    asm volatile("cp.async.wait_group 1;" ::: "memory");
}
__device__ __forceinline__ void cp_wait0() {
    asm volatile("cp.async.wait_group 0;" ::: "memory");
}

// ============================================================================
// K1 (R15 best-measured, unchanged): grouped conv 3x3 (reflect) + BN ->
// exp(logits) + per-group expsum. 16x64 tile, 128 threads, 8 px/thread.
// cp.async double buffer, distance 1, single __syncthreads per chunk
// (prefetch issued after the sync). smem 40.3KB -> 4 blocks/SM.
// ============================================================================
#define K1_TW 64
#define K1_TH 16
#define K1_HALO_R 18
#define K1_HALO_C 66
#define K1_NQ (K1_HALO_R * K1_HALO_C)        // 1188
#define K1_XST 68
#define K1_CHST (K1_HALO_R * K1_XST)         // 1224
#define K1_CHUNK 2
#define K1_NCHUNK (CPG / K1_CHUNK)           // 16
#define K1_BUF_WORDS (K1_CHUNK * K1_CHST)    // 2448
#define K1_WS_BYTES (KK * CPG * KK * 8)                  // 20736
#define K1_SMEM (K1_WS_BYTES + 2 * K1_BUF_WORDS * 4)     // 40320

__global__ void __launch_bounds__(128, 4)
k1_conv_bn(const float* __restrict__ x,
           const float* __restrict__ w,
           const float* __restrict__ gamma,
           const float* __restrict__ beta,
           const float* __restrict__ mean,
           const float* __restrict__ var) {
    extern __shared__ char smem[];
    float2* ws2  = (float2*)smem;                               // [9][32][9]
    float*  bufs = (float*)(smem + K1_WS_BYTES);                // [2][2][1224]

    const int n  = blockIdx.z >> 3;
    const int g  = blockIdx.z & 7;
    const int bx = blockIdx.x * K1_TW;
    const int by = blockIdx.y * K1_TH;
    const int tid = threadIdx.x;
    const int row = tid >> 3;
    const int xq  = (tid & 7) << 3;

    // Register reflect-address tables (10 halo entries per thread)
    int sQ[10], dQ[10];
#pragma unroll
    for (int e = 0; e < 10; e++) {
        int q = tid + e * 128;
        bool ok = (q < K1_NQ);
        int qc = ok ? q : 0;
        int rr = qc / K1_HALO_C;
        int cc = qc - rr * K1_HALO_C;
        sQ[e] = refl(by + rr - 1) * W_IMG + refl(bx + cc - 1);
        dQ[e] = rr * K1_XST + cc;
    }
    const bool hasLast = (tid + 9 * 128) < K1_NQ;
    const uint32_t sbase = smem_u32(bufs);

    // BN-scaled duplicated weights: ws2[o*288 + ci*9 + t]
    for (int i = tid; i < KK * CPG * KK; i += 128) {
        int o  = i / (CPG * KK);
        int oc = g * KK + o;
        float sc = gamma[oc] * rsqrtf(var[oc] + BN_EPS);
        float wv = w[(size_t)oc * (CPG * KK) + (i % (CPG * KK))] * sc;
        ws2[i] = make_float2(wv, wv);
    }

    unsigned long long acc[9][4];
#pragma unroll
    for (int o = 0; o < 9; o++) {
        int oc = g * KK + o;
        float sc = gamma[oc] * rsqrtf(var[oc] + BN_EPS);
        float sh = beta[oc] - mean[oc] * sc;
        unsigned long long p = pack2(sh, sh);
#pragma unroll
        for (int j = 0; j < 4; j++) acc[o][j] = p;
    }

    const float* xg = x + (size_t)(n * C_IN + g * CPG) * HW;

    // Prefetch chunk 0 into buffer 0
#pragma unroll
    for (int ci = 0; ci < K1_CHUNK; ci++) {
        const float* c = xg + (size_t)ci * HW;
        uint32_t boff = (uint32_t)(ci * K1_CHST * 4);
#pragma unroll
        for (int e = 0; e < 9; e++)
            cp_async4(sbase + boff + dQ[e] * 4, c + sQ[e]);
        if (hasLast) cp_async4(sbase + boff + dQ[9] * 4, c + sQ[9]);
    }
    cp_commit();

#pragma unroll 1
    for (int chunk = 0; chunk < K1_NCHUNK; chunk++) {
        cp_wait0();        // chunk's data (committed one compute-phase ago)
        __syncthreads();   // visible to all; prev buffer fully consumed

        // Prefetch chunk+1 into the other buffer (overlaps compute below)
        if (chunk < K1_NCHUNK - 1) {
            const uint32_t bufoff = (uint32_t)((((chunk + 1) & 1)) * K1_BUF_WORDS * 4);
#pragma unroll
            for (int ci = 0; ci < K1_CHUNK; ci++) {
                const float* c = xg + (size_t)((chunk + 1) * K1_CHUNK + ci) * HW;
                uint32_t boff = bufoff + (uint32_t)(ci * K1_CHST * 4);
#pragma unroll
                for (int e = 0; e < 9; e++)
                    cp_async4(sbase + boff + dQ[e] * 4, c + sQ[e]);
                if (hasLast) cp_async4(sbase + boff + dQ[9] * 4, c + sQ[9]);
            }
            cp_commit();
        }

        const float* xsb = bufs + (chunk & 1) * K1_BUF_WORDS;
#pragma unroll
        for (int ci = 0; ci < K1_CHUNK; ci++) {
            const int cig = chunk * K1_CHUNK + ci;
            const float* xrow = xsb + ci * K1_CHST + row * K1_XST + xq;
            const unsigned long long* wb =
                (const unsigned long long*)(ws2) + cig * KK;

#pragma unroll
            for (int r3 = 0; r3 < 3; r3++) {
                float v[10];
                const float4 a0 = *(const float4*)(xrow + r3 * K1_XST);
                const float4 a1 = *(const float4*)(xrow + r3 * K1_XST + 4);
                const float2 a2 = *(const float2*)(xrow + r3 * K1_XST + 8);
                v[0]=a0.x; v[1]=a0.y; v[2]=a0.z; v[3]=a0.w;
                v[4]=a1.x; v[5]=a1.y; v[6]=a1.z; v[7]=a1.w;
                v[8]=a2.x; v[9]=a2.y;

                unsigned long long p[3][4];
#pragma unroll
                for (int c3 = 0; c3 < 3; c3++)
#pragma unroll
                    for (int j = 0; j < 4; j++)
                        p[c3][j] = pack2(v[c3 + 2 * j], v[c3 + 2 * j + 1]);

#pragma unroll
                for (int o = 0; o < 9; o++) {
                    const unsigned long long* wr = wb + o * (CPG * KK) + r3 * 3;
                    unsigned long long w0 = wr[0], w1 = wr[1], w2 = wr[2];
#pragma unroll
                    for (int j = 0; j < 4; j++) fma2(acc[o][j], p[0][j], w0);
#pragma unroll
                    for (int j = 0; j < 4; j++) fma2(acc[o][j], p[1][j], w1);
#pragma unroll
                    for (int j = 0; j < 4; j++) fma2(acc[o][j], p[2][j], w2);
                }
            }
        }
        __syncthreads();   // chunk consumed before next iter's prefetch reuses buffer
    }

    // Epilogue: store EXP(logit) + per-group expsum
    float esum[8] = {0, 0, 0, 0, 0, 0, 0, 0};
    float* lp = g_elog + ((size_t)(n * OC + g * KK) * H_IMG + (by + row)) * W_IMG + bx + xq;
#pragma unroll
    for (int o = 0; o < 9; o++) {
        float4 r0, r1;
        unpack2(acc[o][0], r0.x, r0.y);
        unpack2(acc[o][1], r0.z, r0.w);
        unpack2(acc[o][2], r1.x, r1.y);
        unpack2(acc[o][3], r1.z, r1.w);
        float4 e0 = make_float4(__expf(r0.x), __expf(r0.y), __expf(r0.z), __expf(r0.w));
        float4 e1 = make_float4(__expf(r1.x), __expf(r1.y), __expf(r1.z), __expf(r1.w));
        *(float4*)(lp + (size_t)o * HW)     = e0;
        *(float4*)(lp + (size_t)o * HW + 4) = e1;
        esum[0] += e0.x; esum[1] += e0.y; esum[2] += e0.z; esum[3] += e0.w;
        esum[4] += e1.x; esum[5] += e1.y; esum[6] += e1.z; esum[7] += e1.w;
    }
    float* ep = g_expsum + ((size_t)(n * GROUPS + g) * H_IMG + (by + row)) * W_IMG + bx + xq;
    *(float4*)ep       = make_float4(esum[0], esum[1], esum[2], esum[3]);
    *(float4*)(ep + 4) = make_float4(esum[4], esum[5], esum[6], esum[7]);
}

// ============================================================================
// K3: softmax weights (stored exps / expsum) + weighted 3x3 gather.
// R14 layout (cp.async4 staging, offset-1 dst, 68 stride, 6-LDS gather) +
// R15 ordering (ONE sync per iteration: wait -> sync -> prefetch -> compute).
// 8x64 tile, 256 threads, 2 px/thread, 4 groups per block (1024 blocks).
// 3-buffer ring, distance 2. smem 32.6KB, <=64 regs -> 4 blocks/SM.
// ============================================================================
#define K3_TW 64
#define K3_TH 8
#define K3_HALO_R 10
#define K3_HALO_C 66
#define K3_NQ (K3_HALO_R * K3_HALO_C)    // 660
#define K3_XST 68
#define K3_CHST (K3_HALO_R * K3_XST)     // 680 words per channel
#define K3_BATCH 4
#define K3_NT 32                         // 4 groups x 8 batches
#define K3_BUF_WORDS (K3_BATCH * K3_CHST)   // 2720
#define K3_SMEM (3 * K3_BUF_WORDS * 4)      // 32640

__global__ void __launch_bounds__(256, 4)
k3_softmax_gather(const float* __restrict__ x, float* __restrict__ out) {
    extern __shared__ char smem[];
    float* bufs = (float*)smem;          // [3][4][680]

    const int n    = blockIdx.z >> 1;
    const int g0   = (blockIdx.z & 1) * 4;   // group base for this block
    const int bx = blockIdx.x * K3_TW;
    const int by = blockIdx.y * K3_TH;
    const int tid = threadIdx.x;
    const int ty = tid >> 5;             // 0..7  (warp = one pixel row)
    const int tx = tid & 31;             // cols 2tx, 2tx+1

    // Register reflect-address tables (<=3 entries/thread)
    int sQ[3], dQ[3];
#pragma unroll
    for (int e = 0; e < 3; e++) {
        int q = tid + e * 256;
        int qc = (q < K3_NQ) ? q : 0;
        int rr = qc / K3_HALO_C;
        int cc = qc - rr * K3_HALO_C;
        sQ[e] = refl(by + rr - 1) * W_IMG + refl(bx + cc - 1);
        dQ[e] = rr * K3_XST + cc;
    }
    const bool has3 = (tid + 512) < K3_NQ;

    const float* xb = x + (size_t)n * C_IN * HW;
    const uint32_t sb = smem_u32(bufs);
    const uint32_t du0 = sb + dQ[0] * 4;
    const uint32_t du1 = sb + dQ[1] * 4;
    const uint32_t du2 = sb + dQ[2] * 4;

    // Fill pipeline: batches 0 and 1 (first channels of group g0)
#pragma unroll
    for (int pt = 0; pt < 2; pt++) {
        const uint32_t bufoff = (uint32_t)(pt * K3_BUF_WORDS * 4);
        const int chp = g0 * CPG + pt * K3_BATCH;
#pragma unroll
        for (int ci = 0; ci < K3_BATCH; ci++) {
            const float* c = xb + (size_t)(chp + ci) * HW;
            uint32_t boff = bufoff + (uint32_t)(ci * K3_CHST * 4);
            cp_async4(du0 + boff, c + sQ[0]);
            cp_async4(du1 + boff, c + sQ[1]);
            if (has3) cp_async4(du2 + boff, c + sQ[2]);
        }
        cp_commit();
    }

    // Softmax denominator from K1's per-group expsums (overlaps prefetch)
    const float* eb = g_expsum + ((size_t)(n * GROUPS) * H_IMG + (by + ty)) * W_IMG
                    + bx + 2 * tx;
    float s0 = 0.f, s1 = 0.f;
#pragma unroll
    for (int g = 0; g < 8; g++) {
        float2 ev = *(const float2*)(eb + (size_t)g * HW);
        s0 += ev.x;
        s1 += ev.y;
    }
    const float inv0 = 1.0f / s0;
    const float inv1 = 1.0f / s1;

    const float* lbase = g_elog + ((size_t)n * OC * H_IMG + (by + ty)) * W_IMG
                        + bx + 2 * tx;
    float* ob = out + (size_t)n * C_IN * HW + (size_t)(by + ty) * W_IMG + bx + 2 * tx;
    const int gbase = ty * K3_XST + 2 * tx;

    float sg0[9], sg1[9];
    int bcur = 0;

#pragma unroll 1
    for (int t = 0; t < K3_NT; t++) {
        const int g = g0 + (t >> 3);

        if (t + 1 < K3_NT) cp_wait1(); else cp_wait0();
        __syncthreads();   // batch t visible; buffer (bcur+2)%3 (= iter t-1's,
                           // consumed before this sync) is free for prefetch

        // Prefetch batch t+2 into the freed buffer (overlaps compute below)
        if (t + 2 < K3_NT) {
            const int tt = t + 2;
            const int ch2 = (g0 + (tt >> 3)) * CPG + (tt & 7) * K3_BATCH;
            int bp = bcur + 2; if (bp >= 3) bp -= 3;
            const uint32_t bufoff = (uint32_t)(bp * K3_BUF_WORDS * 4);
#pragma unroll
            for (int ci = 0; ci < K3_BATCH; ci++) {
                const float* c = xb + (size_t)(ch2 + ci) * HW;
                uint32_t boff = bufoff + (uint32_t)(ci * K3_CHST * 4);
                cp_async4(du0 + boff, c + sQ[0]);
                cp_async4(du1 + boff, c + sQ[1]);
                if (has3) cp_async4(du2 + boff, c + sQ[2]);
            }
            cp_commit();
        }

        // sig for this group: stored exp * inv (no expf in K3)
        if ((t & 7) == 0) {
#pragma unroll
            for (int k = 0; k < 9; k++) {
                float2 lv = *(const float2*)(lbase + (size_t)(g * 9 + k) * HW);
                sg0[k] = lv.x * inv0;
                sg1[k] = lv.y * inv1;
            }
        }

        // Compute batch t (6 aligned LDS.64 per channel)
        const float* xbuf = bufs + bcur * K3_BUF_WORDS;
        const int ch = g * CPG + (t & 7) * K3_BATCH;
        float* op = ob + (size_t)ch * HW;
#pragma unroll
        for (int ci = 0; ci < K3_BATCH; ci++) {
            const float* xp = xbuf + ci * K3_CHST + gbase;
            const float2 a0 = *(const float2*)(xp);
            const float2 a1 = *(const float2*)(xp + 2);
            const float2 b0 = *(const float2*)(xp + K3_XST);
            const float2 b1 = *(const float2*)(xp + K3_XST + 2);
            const float2 c0 = *(const float2*)(xp + 2 * K3_XST);
            const float2 c1 = *(const float2*)(xp + 2 * K3_XST + 2);

            float acc0 = sg0[0] * a0.x + sg0[1] * a0.y + sg0[2] * a1.x
                       + sg0[3] * b0.x + sg0[4] * b0.y + sg0[5] * b1.x
                       + sg0[6] * c0.x + sg0[7] * c0.y + sg0[8] * c1.x;
            float acc1 = sg1[0] * a0.y + sg1[1] * a1.x + sg1[2] * a1.y
                       + sg1[3] * b0.y + sg1[4] * b1.x + sg1[5] * b1.y
                       + sg1[6] * c0.y + sg1[7] * c1.x + sg1[8] * c1.y;

            *(float2*)(op + (size_t)ci * HW) = make_float2(acc0, acc1);
        }
        bcur = (bcur + 1 == 3) ? 0 : bcur + 1;
    }
}

// ============================================================================
extern "C" void kernel_launch(void* const* d_in, const int* in_sizes, int n_in,
                              void* d_out, int out_size) {
    const float* x     = (const float*)d_in[0];
    const float* w     = (const float*)d_in[1];
    const float* gamma = (const float*)d_in[2];
    const float* beta  = (const float*)d_in[3];
    const float* mean  = (const float*)d_in[4];
    const float* var   = (const float*)d_in[5];
    float* out = (float*)d_out;

    cudaFuncSetAttribute(k1_conv_bn,
                         cudaFuncAttributeMaxDynamicSharedMemorySize, K1_SMEM);
    cudaFuncSetAttribute(k3_softmax_gather,
                         cudaFuncAttributeMaxDynamicSharedMemorySize, K3_SMEM);

    dim3 g1(W_IMG / K1_TW, H_IMG / K1_TH, N_BATCH * GROUPS);   // (2, 8, 128)
    k1_conv_bn<<<g1, 128, K1_SMEM>>>(x, w, gamma, beta, mean, var);

    dim3 g3(W_IMG / K3_TW, H_IMG / K3_TH, N_BATCH * 2);        // (2, 16, 32)
    k3_softmax_gather<<<g3, 256, K3_SMEM>>>(x, out);
}